// round 2
// baseline (speedup 1.0000x reference)
#include <cuda_runtime.h>
#include <cuda_bf16.h>
#include <math.h>

// ---------------- problem constants ----------------
#define BATCH   512
#define CONFD   128
#define TREATD  2
#define EMBD    256
#define TOPKD   8
#define HIDD    1024
#define NCORP   500000
#define NSPLIT  152          // one CTA per SM (GB300: 152 SMs), disjoint corpus ranges
#define CHUNK   32           // corpus rows staged per iteration
#define SHIN    2176         // CONF + EMB*TOPK

// output layout (float32):
// factual[512] | targeted[512] | cf[1024] | prop_scores[1024] | prop_logits[1024]
// | scores[4096] | idx[4096] | s[262144]
#define OFF_FACT   0
#define OFF_TARG   512
#define OFF_CF     1024
#define OFF_PS     2048
#define OFF_PL     3072
#define OFF_SC     4096
#define OFF_IDX    8192
#define OFF_S      12288

// ---------------- scratch (static device memory; no allocation) ----------------
__device__ float g_peT[EMBD * BATCH];                 // pe as [k/4][b][4], normalized
__device__ float g_rnorm[NCORP];
__device__ float g_cand_s[NSPLIT * BATCH * TOPKD];    // per-CTA exact top-8
__device__ int   g_cand_i[NSPLIT * BATCH * TOPKD];
__device__ int   g_topidx[BATCH * TOPKD];
__device__ float g_xin[BATCH * SHIN];
__device__ float g_tmp[BATCH * HIDD];
__device__ float g_h1[BATCH * HIDD];
__device__ float g_h2[BATCH * HIDD];
__device__ float g_s[BATCH * (HIDD/2)];
__device__ float g_tb[BATCH * 256];
__device__ float g_ob[BATCH * 256];
__device__ float g_gb[BATCH * 256];

// ---------------- K1: pe = normalize(pf @ W_pe + b_pe), stored [k/4][b][4] ----------------
__global__ void pe_kernel(const float* __restrict__ pf,
                          const float* __restrict__ Wpe,
                          const float* __restrict__ bpe) {
    int b = blockIdx.x;           // batch row
    int e = threadIdx.x;          // 256 threads, one output each
    __shared__ float x[CONFD + TREATD];
    __shared__ float red[256];
    if (e < CONFD + TREATD) x[e] = pf[b * (CONFD + TREATD) + e];
    __syncthreads();
    float acc = bpe[e];
    #pragma unroll 10
    for (int k = 0; k < CONFD + TREATD; ++k)
        acc = fmaf(x[k], Wpe[k * EMBD + e], acc);
    red[e] = acc * acc;
    __syncthreads();
    for (int s = 128; s > 0; s >>= 1) {
        if (e < s) red[e] += red[e + s];
        __syncthreads();
    }
    float rn = 1.0f / fmaxf(sqrtf(red[0]), 1e-12f);
    // layout: [e>>2][b][e&3]
    g_peT[((e >> 2) * BATCH + b) * 4 + (e & 3)] = acc * rn;
}

// ---------------- K2: corpus reciprocal norms ----------------
__global__ void rnorm_kernel(const float* __restrict__ corpus) {
    int w    = blockIdx.x * 8 + (threadIdx.x >> 5);   // warp id == corpus row
    int lane = threadIdx.x & 31;
    if (w >= NCORP) return;
    const float4* r = (const float4*)(corpus + (size_t)w * EMBD);
    float4 v0 = r[lane * 2 + 0];
    float4 v1 = r[lane * 2 + 1];
    float ss = v0.x*v0.x + v0.y*v0.y + v0.z*v0.z + v0.w*v0.w
             + v1.x*v1.x + v1.y*v1.y + v1.z*v1.z + v1.w*v1.w;
    #pragma unroll
    for (int o = 16; o; o >>= 1) ss += __shfl_xor_sync(0xFFFFFFFFu, ss, o);
    if (lane == 0) g_rnorm[w] = 1.0f / fmaxf(sqrtf(ss), 1e-12f);
}

// ---------------- K3: fused sim GEMM (f32x2) + per-CTA exact top-8 ----------------
// grid = NSPLIT CTAs, 512 threads; thread t owns batch row t exclusively.
__global__ void __launch_bounds__(512, 1)
sim_topk_kernel(const float* __restrict__ corpus) {
    extern __shared__ float smem[];
    float4* B4  = (float4*)smem;              // CHUNK rows x 64 float4
    float*  rns = smem + CHUNK * EMBD;        // CHUNK floats
    const ulonglong2* B2 = (const ulonglong2*)smem;
    const float4* peT4 = (const float4*)g_peT;   // [kq][b]
    const int t = threadIdx.x;
    const int c = blockIdx.x;
    const long start = ((long)c       * NCORP) / NSPLIT;
    const long end   = ((long)(c + 1) * NCORP) / NSPLIT;

    float s8[TOPKD];
    int   i8[TOPKD];
    #pragma unroll
    for (int q = 0; q < TOPKD; ++q) { s8[q] = -INFINITY; i8[q] = -1; }

    for (long base = start; base < end; base += CHUNK) {
        int count = (int)((end - base < CHUNK) ? (end - base) : CHUNK);
        // stage corpus chunk (row-major, float4)
        const float4* src = ((const float4*)corpus) + base * 64;
        for (int p = t; p < count * 64; p += 512) B4[p] = src[p];
        if (t < CHUNK) rns[t] = (t < count) ? g_rnorm[base + t] : 0.0f;
        __syncthreads();

        unsigned long long acc2[CHUNK];
        #pragma unroll
        for (int j = 0; j < CHUNK; ++j) acc2[j] = 0ULL;

        for (int kq = 0; kq < EMBD / 4; ++kq) {
            float4 a = peT4[kq * BATCH + t];
            unsigned long long a01, a23;
            asm("mov.b64 %0, {%1, %2};" : "=l"(a01) : "f"(a.x), "f"(a.y));
            asm("mov.b64 %0, {%1, %2};" : "=l"(a23) : "f"(a.z), "f"(a.w));
            #pragma unroll
            for (int j = 0; j < CHUNK; ++j) {
                ulonglong2 bb = B2[j * 64 + kq];   // same addr across warp: broadcast
                asm("fma.rn.f32x2 %0, %1, %2, %0;" : "+l"(acc2[j]) : "l"(a01), "l"(bb.x));
                asm("fma.rn.f32x2 %0, %1, %2, %0;" : "+l"(acc2[j]) : "l"(a23), "l"(bb.y));
            }
        }

        // top-8 scan (registers only)
        #pragma unroll
        for (int j = 0; j < CHUNK; ++j) {
            float lo, hi;
            asm("mov.b64 {%0, %1}, %2;" : "=f"(lo), "=f"(hi) : "l"(acc2[j]));
            float sim = (lo + hi) * rns[j];
            if (j < count && sim > s8[TOPKD - 1]) {
                float v = sim; int vi = (int)(base + j);
                #pragma unroll
                for (int q = 0; q < TOPKD; ++q) {
                    if (v > s8[q]) {
                        float ts = s8[q]; int ti = i8[q];
                        s8[q] = v; i8[q] = vi; v = ts; vi = ti;
                    }
                }
            }
        }
        __syncthreads();
    }
    #pragma unroll
    for (int q = 0; q < TOPKD; ++q) {
        g_cand_s[(c * BATCH + t) * TOPKD + q] = s8[q];
        g_cand_i[(c * BATCH + t) * TOPKD + q] = i8[q];
    }
}

// ---------------- K4: exact global top-8 merge ----------------
__global__ void merge_kernel(float* __restrict__ out) {
    const int b = blockIdx.x;
    const int t = threadIdx.x;     // 256
    __shared__ float cs[NSPLIT * TOPKD];
    __shared__ int   ci[NSPLIT * TOPKD];
    __shared__ float rs[256];
    __shared__ int   ri[256];
    __shared__ int   sel_i;
    const int NC = NSPLIT * TOPKD;   // 1216
    for (int p = t; p < NC; p += 256) {
        int c = p >> 3, q = p & 7;
        cs[p] = g_cand_s[(c * BATCH + b) * TOPKD + q];
        ci[p] = g_cand_i[(c * BATCH + b) * TOPKD + q];
    }
    __syncthreads();
    for (int r = 0; r < TOPKD; ++r) {
        float bs = -INFINITY; int bi = 0x7FFFFFFF;
        for (int p = t; p < NC; p += 256) {
            float v = cs[p]; int vi = ci[p];
            if (v > bs || (v == bs && vi < bi)) { bs = v; bi = vi; }
        }
        rs[t] = bs; ri[t] = bi;
        __syncthreads();
        for (int s = 128; s > 0; s >>= 1) {
            if (t < s) {
                if (rs[t + s] > rs[t] || (rs[t + s] == rs[t] && ri[t + s] < ri[t])) {
                    rs[t] = rs[t + s]; ri[t] = ri[t + s];
                }
            }
            __syncthreads();
        }
        if (t == 0) {
            sel_i = ri[0];
            out[OFF_SC  + b * TOPKD + r] = rs[0];
            out[OFF_IDX + b * TOPKD + r] = (float)ri[0];
            g_topidx[b * TOPKD + r] = ri[0];
        }
        __syncthreads();
        for (int p = t; p < NC; p += 256)
            if (ci[p] == sel_i) cs[p] = -INFINITY;
        __syncthreads();
    }
}

// ---------------- K5: build shared_in = [conf | retrieved(raw)] ----------------
__global__ void gather_kernel(const float* __restrict__ conf,
                              const float* __restrict__ corpus) {
    int b = blockIdx.x, t = threadIdx.x;   // 256
    if (t < CONFD) g_xin[b * SHIN + t] = conf[b * CONFD + t];
    #pragma unroll
    for (int ki = 0; ki < TOPKD; ++ki) {
        int j = g_topidx[b * TOPKD + ki];
        g_xin[b * SHIN + CONFD + ki * EMBD + t] = corpus[(size_t)j * EMBD + t];
    }
}

// ---------------- generic fp32 GEMM: C = act(A@B + bias) ----------------
// M%64==0, N%64==0, K%16==0. 256 threads, 64x64 tile, 4x4 per thread.
template <int ACT>
__global__ void __launch_bounds__(256)
gemm_kernel(const float* __restrict__ A, const float* __restrict__ Bm,
            const float* __restrict__ bias, float* __restrict__ C,
            int M, int N, int K) {
    __shared__ float As[16][68];
    __shared__ float Bs[16][64];
    const int tx = threadIdx.x & 15;
    const int ty = threadIdx.x >> 4;
    const int m0 = blockIdx.y * 64;
    const int n0 = blockIdx.x * 64;
    float acc[4][4];
    #pragma unroll
    for (int r = 0; r < 4; ++r)
        #pragma unroll
        for (int cc = 0; cc < 4; ++cc) acc[r][cc] = 0.0f;

    const int p = threadIdx.x * 4;
    const int am = p >> 4, ak = p & 15;     // A-tile element
    const int bk = p >> 6, bn = p & 63;     // B-tile element
    for (int k0 = 0; k0 < K; k0 += 16) {
        float4 av = *(const float4*)&A[(size_t)(m0 + am) * K + k0 + ak];
        As[ak + 0][am] = av.x; As[ak + 1][am] = av.y;
        As[ak + 2][am] = av.z; As[ak + 3][am] = av.w;
        *(float4*)&Bs[bk][bn] = *(const float4*)&Bm[(size_t)(k0 + bk) * N + n0 + bn];
        __syncthreads();
        #pragma unroll
        for (int k = 0; k < 16; ++k) {
            float4 a4 = *(float4*)&As[k][ty * 4];
            float4 b4 = *(float4*)&Bs[k][tx * 4];
            float a[4] = {a4.x, a4.y, a4.z, a4.w};
            float bb[4] = {b4.x, b4.y, b4.z, b4.w};
            #pragma unroll
            for (int r = 0; r < 4; ++r)
                #pragma unroll
                for (int cc = 0; cc < 4; ++cc)
                    acc[r][cc] = fmaf(a[r], bb[cc], acc[r][cc]);
        }
        __syncthreads();
    }
    #pragma unroll
    for (int r = 0; r < 4; ++r) {
        int row = m0 + ty * 4 + r;
        float4 o;
        float* po = &o.x;
        #pragma unroll
        for (int cc = 0; cc < 4; ++cc) {
            int col = n0 + tx * 4 + cc;
            float v = acc[r][cc] + bias[col];
            if (ACT == 1) v = fmaxf(v, 0.0f);
            po[cc] = v;
        }
        *(float4*)&C[(size_t)row * N + n0 + tx * 4] = o;
    }
}

// ---------------- LayerNorm over 1024-wide rows ----------------
__global__ void ln_kernel(const float* __restrict__ X, const float* __restrict__ g,
                          const float* __restrict__ be, float* __restrict__ Y) {
    int b = blockIdx.x, t = threadIdx.x;   // 256 threads, 4 elems each
    __shared__ float r1[256], r2[256];
    float4 x = ((const float4*)(X + (size_t)b * HIDD))[t];
    r1[t] = x.x + x.y + x.z + x.w;
    r2[t] = x.x*x.x + x.y*x.y + x.z*x.z + x.w*x.w;
    __syncthreads();
    for (int s = 128; s > 0; s >>= 1) {
        if (t < s) { r1[t] += r1[t + s]; r2[t] += r2[t + s]; }
        __syncthreads();
    }
    float mu  = r1[0] * (1.0f / HIDD);
    float var = r2[0] * (1.0f / HIDD) - mu * mu;
    float rstd = rsqrtf(var + 1e-5f);
    float4 gg = ((const float4*)g)[t];
    float4 bb = ((const float4*)be)[t];
    float4 y;
    y.x = (x.x - mu) * rstd * gg.x + bb.x;
    y.y = (x.y - mu) * rstd * gg.y + bb.y;
    y.z = (x.z - mu) * rstd * gg.z + bb.z;
    y.w = (x.w - mu) * rstd * gg.w + bb.w;
    ((float4*)(Y + (size_t)b * HIDD))[t] = y;
}

// ---------------- propensity head: logits + softmax ----------------
__global__ void prop_kernel(const float* __restrict__ Wt2, const float* __restrict__ bt2,
                            float* __restrict__ out) {
    int b = blockIdx.x, t = threadIdx.x;   // 256
    __shared__ float r0[256], r1[256];
    float v = g_tb[b * 256 + t];
    r0[t] = v * Wt2[t * 2 + 0];
    r1[t] = v * Wt2[t * 2 + 1];
    __syncthreads();
    for (int s = 128; s > 0; s >>= 1) {
        if (t < s) { r0[t] += r0[t + s]; r1[t] += r1[t + s]; }
        __syncthreads();
    }
    if (t == 0) {
        float l0 = r0[0] + bt2[0];
        float l1 = r1[0] + bt2[1];
        out[OFF_PL + b * 2 + 0] = l0;
        out[OFF_PL + b * 2 + 1] = l1;
        float m = fmaxf(l0, l1);
        float e0 = expf(l0 - m), e1 = expf(l1 - m);
        float d = 1.0f / (e0 + e1);
        out[OFF_PS + b * 2 + 0] = e0 * d;
        out[OFF_PS + b * 2 + 1] = e1 * d;
    }
}

// ---------------- outcome / targeted / counterfactual heads ----------------
__global__ void heads_kernel(const float* __restrict__ treat,
                             const float* __restrict__ Wo1, const float* __restrict__ Wo2,
                             const float* __restrict__ bo2,
                             const float* __restrict__ Wg1, const float* __restrict__ Wg2,
                             const float* __restrict__ bg2,
                             float* __restrict__ out) {
    int b = blockIdx.x, t = threadIdx.x;   // 256
    __shared__ float r[4][256];
    float obv = g_ob[b * 256 + t];
    float gbv = g_gb[b * 256 + t];
    float wo0 = Wo1[(size_t)512 * 256 + t];
    float wo1 = Wo1[(size_t)513 * 256 + t];
    float wg0 = Wg1[(size_t)512 * 256 + t];
    float wg1 = Wg1[(size_t)513 * 256 + t];
    float t0 = treat[b * 2 + 0], t1 = treat[b * 2 + 1];
    float wo2 = Wo2[t], wg2 = Wg2[t];
    r[0][t] = fmaxf(obv + t0 * wo0 + t1 * wo1, 0.0f) * wo2;   // factual
    r[1][t] = fmaxf(gbv + t0 * wg0 + t1 * wg1, 0.0f) * wg2;   // targeted
    r[2][t] = fmaxf(obv + wo0, 0.0f) * wo2;                   // cf t=0
    r[3][t] = fmaxf(obv + wo1, 0.0f) * wo2;                   // cf t=1
    __syncthreads();
    for (int s = 128; s > 0; s >>= 1) {
        if (t < s) {
            r[0][t] += r[0][t + s]; r[1][t] += r[1][t + s];
            r[2][t] += r[2][t + s]; r[3][t] += r[3][t + s];
        }
        __syncthreads();
    }
    if (t == 0) {
        out[OFF_FACT + b]       = r[0][0] + bo2[0];
        out[OFF_TARG + b]       = r[1][0] + bg2[0];
        out[OFF_CF + b * 2 + 0] = r[2][0] + bo2[0];
        out[OFF_CF + b * 2 + 1] = r[3][0] + bo2[0];
    }
}

// ---------------- copy s into output ----------------
__global__ void copy_s_kernel(float* __restrict__ out) {
    int i = blockIdx.x * 256 + threadIdx.x;
    out[OFF_S + i] = g_s[i];
}

// ---------------- launch ----------------
extern "C" void kernel_launch(void* const* d_in, const int* in_sizes, int n_in,
                              void* d_out, int out_size) {
    const float* pf     = (const float*)d_in[0];
    const float* treat  = (const float*)d_in[1];
    const float* conf   = (const float*)d_in[2];
    const float* corpus = (const float*)d_in[3];
    const float* Wpe    = (const float*)d_in[4];
    const float* bpe    = (const float*)d_in[5];
    const float* W1     = (const float*)d_in[6];
    const float* b1     = (const float*)d_in[7];
    const float* g1     = (const float*)d_in[8];
    const float* be1    = (const float*)d_in[9];
    const float* W2     = (const float*)d_in[10];
    const float* b2     = (const float*)d_in[11];
    const float* g2     = (const float*)d_in[12];
    const float* be2    = (const float*)d_in[13];
    const float* W3     = (const float*)d_in[14];
    const float* b3     = (const float*)d_in[15];
    const float* Wo1    = (const float*)d_in[16];
    const float* bo1    = (const float*)d_in[17];
    const float* Wo2    = (const float*)d_in[18];
    const float* bo2    = (const float*)d_in[19];
    const float* Wt1    = (const float*)d_in[20];
    const float* bt1    = (const float*)d_in[21];
    const float* Wt2    = (const float*)d_in[22];
    const float* bt2    = (const float*)d_in[23];
    const float* Wg1    = (const float*)d_in[24];
    const float* bg1    = (const float*)d_in[25];
    const float* Wg2    = (const float*)d_in[26];
    const float* bg2    = (const float*)d_in[27];
    float* out = (float*)d_out;

    // resolve device-scratch addresses (host code cannot use __device__ symbols directly!)
    float *p_xin, *p_tmp, *p_h1, *p_h2, *p_s, *p_tb, *p_ob, *p_gb;
    cudaGetSymbolAddress((void**)&p_xin, g_xin);
    cudaGetSymbolAddress((void**)&p_tmp, g_tmp);
    cudaGetSymbolAddress((void**)&p_h1,  g_h1);
    cudaGetSymbolAddress((void**)&p_h2,  g_h2);
    cudaGetSymbolAddress((void**)&p_s,   g_s);
    cudaGetSymbolAddress((void**)&p_tb,  g_tb);
    cudaGetSymbolAddress((void**)&p_ob,  g_ob);
    cudaGetSymbolAddress((void**)&p_gb,  g_gb);

    // retrieval
    pe_kernel<<<BATCH, 256>>>(pf, Wpe, bpe);
    rnorm_kernel<<<NCORP / 8, 256>>>(corpus);
    size_t simSmem = (size_t)(CHUNK * EMBD + CHUNK) * sizeof(float);
    sim_topk_kernel<<<NSPLIT, 512, simSmem>>>(corpus);
    merge_kernel<<<BATCH, 256>>>(out);
    gather_kernel<<<BATCH, 256>>>(conf, corpus);

    // shared encoder
    gemm_kernel<1><<<dim3(HIDD / 64, BATCH / 64), 256>>>(p_xin, W1, b1, p_tmp,
                                                         BATCH, HIDD, SHIN);
    ln_kernel<<<BATCH, 256>>>(p_tmp, g1, be1, p_h1);
    gemm_kernel<1><<<dim3(HIDD / 64, BATCH / 64), 256>>>(p_h1, W2, b2, p_tmp,
                                                         BATCH, HIDD, HIDD);
    ln_kernel<<<BATCH, 256>>>(p_tmp, g2, be2, p_h2);
    gemm_kernel<0><<<dim3((HIDD / 2) / 64, BATCH / 64), 256>>>(p_h2, W3, b3, p_s,
                                                               BATCH, HIDD / 2, HIDD);

    // heads
    gemm_kernel<1><<<dim3(256 / 64, BATCH / 64), 256>>>(p_s, Wt1, bt1, p_tb,
                                                        BATCH, 256, HIDD / 2);
    gemm_kernel<0><<<dim3(256 / 64, BATCH / 64), 256>>>(p_s, Wo1, bo1, p_ob,
                                                        BATCH, 256, HIDD / 2);
    gemm_kernel<0><<<dim3(256 / 64, BATCH / 64), 256>>>(p_s, Wg1, bg1, p_gb,
                                                        BATCH, 256, HIDD / 2);
    prop_kernel<<<BATCH, 256>>>(Wt2, bt2, out);
    heads_kernel<<<BATCH, 256>>>(treat, Wo1, Wo2, bo2, Wg1, Wg2, bg2, out);
    copy_s_kernel<<<(BATCH * (HIDD / 2)) / 256, 256>>>(out);
}

// round 6
// speedup vs baseline: 2.5694x; 2.5694x over previous
#include <cuda_runtime.h>
#include <cuda_bf16.h>
#include <math.h>
#include <stdint.h>

// ---------------- problem constants ----------------
#define BATCH   512
#define CONFD   128
#define TREATD  2
#define EMBD    256
#define TOPKD   8
#define HIDD    1024
#define NCORP   500000
#define NSPLIT  152
#define NTILES  3907            // ceil(500000/128)
#define NPAD    (NTILES*128)    // 500096
#define NL      (NSPLIT*8)      // 1216 candidate lists per batch row
#define NCAND   16              // coarse candidates rescored exactly
#define SHIN    2176

// key for empty top-8 slot: encode(-inf) in high 32 bits -> decodes to -inf
#define KEY_EMPTY 0x007FFFFF00000000ULL

// output layout (float32)
#define OFF_FACT   0
#define OFF_TARG   512
#define OFF_CF     1024
#define OFF_PS     2048
#define OFF_PL     3072
#define OFF_SC     4096
#define OFF_IDX    8192
#define OFF_S      12288

// ---------------- static device scratch ----------------
__device__ __align__(16) __nv_bfloat16 g_corpusH[(size_t)NPAD * EMBD];  // row-major bf16
__device__ __align__(16) __nv_bfloat16 g_peH[BATCH * EMBD];             // row-major bf16
__device__ float g_peN[BATCH * EMBD];                // normalized pe fp32 row-major
__device__ float g_rnorm[NCORP];
__device__ unsigned long long g_cand[(size_t)BATCH * NL * TOPKD];
__device__ int   g_coarse[BATCH * NCAND];
__device__ int   g_topidx[BATCH * TOPKD];
__device__ float g_xin[BATCH * SHIN];
__device__ float g_tmp[BATCH * HIDD];
__device__ float g_h1[BATCH * HIDD];
__device__ float g_h2[BATCH * HIDD];
__device__ float g_s[BATCH * (HIDD/2)];
__device__ float g_tb[BATCH * 256];
__device__ float g_ob[BATCH * 256];
__device__ float g_gb[BATCH * 256];

__device__ __forceinline__ uint32_t smem_u32(const void* p) {
    uint32_t a;
    asm("{ .reg .u64 t; cvta.to.shared.u64 t, %1; cvt.u32.u64 %0, t; }" : "=r"(a) : "l"(p));
    return a;
}

// ---------------- K1: pe = normalize(pf @ W_pe + b_pe) ----------------
__global__ void pe_kernel(const float* __restrict__ pf,
                          const float* __restrict__ Wpe,
                          const float* __restrict__ bpe) {
    int b = blockIdx.x;
    int e = threadIdx.x;          // 256
    __shared__ float x[CONFD + TREATD];
    __shared__ float red[256];
    if (e < CONFD + TREATD) x[e] = pf[b * (CONFD + TREATD) + e];
    __syncthreads();
    float acc = bpe[e];
    #pragma unroll 10
    for (int k = 0; k < CONFD + TREATD; ++k)
        acc = fmaf(x[k], Wpe[k * EMBD + e], acc);
    red[e] = acc * acc;
    __syncthreads();
    for (int s = 128; s > 0; s >>= 1) {
        if (e < s) red[e] += red[e + s];
        __syncthreads();
    }
    float v = acc / fmaxf(sqrtf(red[0]), 1e-12f);
    g_peN[b * EMBD + e] = v;
    g_peH[b * EMBD + e] = __float2bfloat16(v);
}

// ---------------- K2: corpus -> bf16 row-major + rnorm ----------------
__global__ void convert_kernel(const float* __restrict__ corpus) {
    int row  = blockIdx.x * 8 + (threadIdx.x >> 5);
    int lane = threadIdx.x & 31;
    if (row >= NPAD) return;
    float v[8];
    if (row < NCORP) {
        const float4* r4 = (const float4*)(corpus + (size_t)row * EMBD);
        float4 a = r4[lane * 2 + 0], b = r4[lane * 2 + 1];
        v[0]=a.x; v[1]=a.y; v[2]=a.z; v[3]=a.w; v[4]=b.x; v[5]=b.y; v[6]=b.z; v[7]=b.w;
    } else {
        #pragma unroll
        for (int i = 0; i < 8; ++i) v[i] = 0.0f;
    }
    float ss = 0.0f;
    #pragma unroll
    for (int i = 0; i < 8; ++i) ss = fmaf(v[i], v[i], ss);
    #pragma unroll
    for (int o = 16; o; o >>= 1) ss += __shfl_xor_sync(0xFFFFFFFFu, ss, o);
    if (lane == 0 && row < NCORP) g_rnorm[row] = 1.0f / fmaxf(sqrtf(ss), 1e-12f);
    union { __nv_bfloat16 h[8]; uint4 u; } pk;
    #pragma unroll
    for (int i = 0; i < 8; ++i) pk.h[i] = __float2bfloat16(v[i]);
    ((uint4*)g_corpusH)[(size_t)row * 32 + lane] = pk.u;
}

// ---------------- K3: mma.sync bf16 sim + per-thread coarse top-8 ----------------
// smem: peS [0,65536)  ctile [65536,131072)  rns [131072,131584)
#define SIM_SMEM 131584

#define PROC(karr, smin, simv, grow) do {                                             \
    if ((grow) < NCORP && (simv) >= (smin)) {                                         \
        uint32_t _u = __float_as_uint(simv);                                          \
        _u ^= (((int)_u) < 0) ? 0xFFFFFFFFu : 0x80000000u;                            \
        unsigned long long _k = ((unsigned long long)_u << 32)                        \
                              | (unsigned long long)(0xFFFFFFFFu - (uint32_t)(grow)); \
        if (_k > karr[7]) {                                                           \
            _Pragma("unroll")                                                         \
            for (int _q = 0; _q < 8; ++_q)                                            \
                if (_k > karr[_q]) {                                                  \
                    unsigned long long _t2 = karr[_q]; karr[_q] = _k; _k = _t2;       \
                }                                                                     \
            uint32_t _hi = (uint32_t)(karr[7] >> 32);                                 \
            _hi ^= (((int)_hi) < 0) ? 0x80000000u : 0xFFFFFFFFu;                      \
            smin = __uint_as_float(_hi);                                              \
        }                                                                             \
    }                                                                                 \
} while (0)

__global__ void __launch_bounds__(512, 1) sim_kernel() {
    extern __shared__ __align__(16) unsigned char sm[];
    const uint32_t smb = smem_u32(sm);
    float* rns_s = (float*)(sm + 131072);
    const int t = threadIdx.x, lane = t & 31, w = t >> 5;
    const int c = blockIdx.x;
    const int mblk = w >> 1, ns = w & 1;
    const int gid = lane >> 2, tid4 = lane & 3;
    const int T0 = (c * NTILES) / NSPLIT, T1 = ((c + 1) * NTILES) / NSPLIT;

    // ldmatrix per-lane bases (XOR-swizzled rows of 512B)
    const uint32_t swz   = (uint32_t)(lane & 7) << 4;
    const uint32_t offA0 = (uint32_t)((lane >> 4) * 16);
    const uint32_t Abase = smb + (uint32_t)(mblk * 16 + (lane & 15)) * 512;
    const uint32_t offB0 = (uint32_t)(((lane >> 3) & 1) * 16);
    const uint32_t Bbase = smb + 65536 + (uint32_t)(ns * 64 + (lane & 7)) * 512;

    for (int h = 0; h < 4; ++h) {
        // stage pe quarter (128 rows x 512B), swizzled
        {
            const uint4* src = (const uint4*)g_peH + (size_t)(h * 128) * 32;
            #pragma unroll
            for (int u = t; u < 4096; u += 512) {
                int r = u >> 5, un = u & 31;
                *(uint4*)(sm + r * 512 + ((un * 16) ^ ((r & 7) << 4))) = src[u];
            }
        }
        unsigned long long k8a[8], k8b[8];
        #pragma unroll
        for (int q = 0; q < 8; ++q) { k8a[q] = KEY_EMPTY; k8b[q] = KEY_EMPTY; }
        float smin0 = -INFINITY, smin1 = -INFINITY;
        __syncthreads();

        for (int tile = T0; tile < T1; ++tile) {
            // stage corpus tile (128 rows x 512B), swizzled
            {
                const uint4* src = (const uint4*)g_corpusH + (size_t)tile * 4096;
                #pragma unroll
                for (int u = t; u < 4096; u += 512) {
                    int r = u >> 5, un = u & 31;
                    *(uint4*)(sm + 65536 + r * 512 + ((un * 16) ^ ((r & 7) << 4))) = src[u];
                }
            }
            if (t < 128) {
                int rr = tile * 128 + t;
                rns_s[t] = (rr < NCORP) ? g_rnorm[rr] : 0.0f;
            }
            __syncthreads();

            float acc[8][4];
            #pragma unroll
            for (int nf = 0; nf < 8; ++nf)
                #pragma unroll
                for (int i = 0; i < 4; ++i) acc[nf][i] = 0.0f;

            #pragma unroll
            for (int ks = 0; ks < 16; ++ks) {
                uint32_t a0, a1, a2, a3;
                uint32_t aaddr = Abase + (((uint32_t)(ks * 32) + offA0) ^ swz);
                asm volatile("ldmatrix.sync.aligned.m8n8.x4.shared.b16 {%0,%1,%2,%3}, [%4];"
                             : "=r"(a0), "=r"(a1), "=r"(a2), "=r"(a3) : "r"(aaddr));
                uint32_t koffB = ((uint32_t)(ks * 32) + offB0) ^ swz;
                #pragma unroll
                for (int nf = 0; nf < 8; ++nf) {
                    uint32_t b0, b1;
                    uint32_t baddr = Bbase + (uint32_t)(nf * 4096) + koffB;
                    asm volatile("ldmatrix.sync.aligned.m8n8.x2.shared.b16 {%0,%1}, [%2];"
                                 : "=r"(b0), "=r"(b1) : "r"(baddr));
                    asm volatile("mma.sync.aligned.m16n8k16.row.col.f32.bf16.bf16.f32 "
                                 "{%0,%1,%2,%3}, {%4,%5,%6,%7}, {%8,%9}, {%0,%1,%2,%3};"
                                 : "+f"(acc[nf][0]), "+f"(acc[nf][1]),
                                   "+f"(acc[nf][2]), "+f"(acc[nf][3])
                                 : "r"(a0), "r"(a1), "r"(a2), "r"(a3), "r"(b0), "r"(b1));
                }
            }

            // epilogue: top-8 update (rows gid / gid+8, cols tid4*2+{0,1} per nfrag)
            #pragma unroll
            for (int nf = 0; nf < 8; ++nf) {
                int col0 = ns * 64 + nf * 8 + tid4 * 2;
                float rn0 = rns_s[col0], rn1 = rns_s[col0 + 1];
                int grow0 = tile * 128 + col0;
                float s00 = acc[nf][0] * rn0;
                float s01 = acc[nf][1] * rn1;
                float s10 = acc[nf][2] * rn0;
                float s11 = acc[nf][3] * rn1;
                PROC(k8a, smin0, s00, grow0);
                PROC(k8a, smin0, s01, grow0 + 1);
                PROC(k8b, smin1, s10, grow0);
                PROC(k8b, smin1, s11, grow0 + 1);
            }
            __syncthreads();   // before restaging ctile
        }

        // flush candidate lists for this quarter
        {
            const int list = c * 8 + ns * 4 + tid4;
            int row0 = h * 128 + mblk * 16 + gid;
            unsigned long long* d0 = g_cand + ((size_t)row0 * NL + list) * TOPKD;
            unsigned long long* d1 = g_cand + ((size_t)(row0 + 8) * NL + list) * TOPKD;
            #pragma unroll
            for (int q = 0; q < 8; ++q) { d0[q] = k8a[q]; d1[q] = k8b[q]; }
        }
        __syncthreads();       // before pe restage next quarter
    }
}

// ---------------- K4: merge coarse candidates -> top-16 per row ----------------
#define MERGE_SMEM (NL * TOPKD * 8)   // 77824 bytes
__global__ void merge_kernel() {
    extern __shared__ unsigned long long cs[];   // NL*8 = 9728
    __shared__ unsigned long long rk[256];
    __shared__ int rp[256];
    const int b = blockIdx.x;
    const int t = threadIdx.x;     // 256
    const int NC = NL * TOPKD;     // 9728
    for (int p = t; p < NC; p += 256) cs[p] = g_cand[(size_t)b * NC + p];
    __syncthreads();
    for (int r = 0; r < NCAND; ++r) {
        unsigned long long bk = 0ULL; int bp = 0;
        for (int p = t; p < NC; p += 256)
            if (cs[p] > bk) { bk = cs[p]; bp = p; }
        rk[t] = bk; rp[t] = bp;
        __syncthreads();
        for (int s = 128; s > 0; s >>= 1) {
            if (t < s && rk[t + s] > rk[t]) { rk[t] = rk[t + s]; rp[t] = rp[t + s]; }
            __syncthreads();
        }
        if (t == 0) {
            g_coarse[b * NCAND + r] = (int)(0xFFFFFFFFu - (uint32_t)rk[0]);
            cs[rp[0]] = 0ULL;
        }
        __syncthreads();
    }
}

// ---------------- K5: exact fp32 rescore of 16 candidates -> top-8 ----------------
__global__ void rescore_kernel(const float* __restrict__ corpus, float* __restrict__ out) {
    const int b = blockIdx.x;
    const int w = threadIdx.x >> 5;      // 16 warps = 16 candidates
    const int lane = threadIdx.x & 31;
    __shared__ float sc[NCAND];
    __shared__ int   si[NCAND];
    int idx = g_coarse[b * NCAND + w];
    const float4* cr = (const float4*)(corpus + (size_t)idx * EMBD);
    const float4* pr = (const float4*)(g_peN + (size_t)b * EMBD);
    float dot = 0.0f, ss = 0.0f;
    #pragma unroll
    for (int i = 0; i < 2; ++i) {
        float4 cv = cr[lane * 2 + i];
        float4 pv = pr[lane * 2 + i];
        dot = fmaf(pv.x, cv.x, fmaf(pv.y, cv.y, fmaf(pv.z, cv.z, fmaf(pv.w, cv.w, dot))));
        ss  = fmaf(cv.x, cv.x, fmaf(cv.y, cv.y, fmaf(cv.z, cv.z, fmaf(cv.w, cv.w, ss))));
    }
    #pragma unroll
    for (int o = 16; o; o >>= 1) {
        dot += __shfl_xor_sync(0xFFFFFFFFu, dot, o);
        ss  += __shfl_xor_sync(0xFFFFFFFFu, ss,  o);
    }
    if (lane == 0) { sc[w] = dot / fmaxf(sqrtf(ss), 1e-12f); si[w] = idx; }
    __syncthreads();
    if (threadIdx.x == 0) {
        #pragma unroll
        for (int r = 0; r < TOPKD; ++r) {
            int best = r;
            for (int q = r + 1; q < NCAND; ++q)
                if (sc[q] > sc[best] || (sc[q] == sc[best] && si[q] < si[best])) best = q;
            float tv = sc[r]; sc[r] = sc[best]; sc[best] = tv;
            int   ti = si[r]; si[r] = si[best]; si[best] = ti;
            out[OFF_SC  + b * TOPKD + r] = sc[r];
            out[OFF_IDX + b * TOPKD + r] = (float)si[r];
            g_topidx[b * TOPKD + r] = si[r];
        }
    }
}

// ---------------- K6: build shared_in = [conf | retrieved(raw)] ----------------
__global__ void gather_kernel(const float* __restrict__ conf,
                              const float* __restrict__ corpus) {
    int b = blockIdx.x, t = threadIdx.x;   // 256
    if (t < CONFD) g_xin[b * SHIN + t] = conf[b * CONFD + t];
    #pragma unroll
    for (int ki = 0; ki < TOPKD; ++ki) {
        int j = g_topidx[b * TOPKD + ki];
        g_xin[b * SHIN + CONFD + ki * EMBD + t] = corpus[(size_t)j * EMBD + t];
    }
}

// ---------------- generic fp32 GEMM: C = act(A@B + bias) ----------------
template <int ACT>
__global__ void __launch_bounds__(256)
gemm_kernel(const float* __restrict__ A, const float* __restrict__ Bm,
            const float* __restrict__ bias, float* __restrict__ C,
            int M, int N, int K) {
    __shared__ float As[16][68];
    __shared__ float Bs[16][64];
    const int tx = threadIdx.x & 15;
    const int ty = threadIdx.x >> 4;
    const int m0 = blockIdx.y * 64;
    const int n0 = blockIdx.x * 64;
    float acc[4][4];
    #pragma unroll
    for (int r = 0; r < 4; ++r)
        #pragma unroll
        for (int cc = 0; cc < 4; ++cc) acc[r][cc] = 0.0f;

    const int p = threadIdx.x * 4;
    const int am = p >> 4, ak = p & 15;
    const int bk = p >> 6, bn = p & 63;
    for (int k0 = 0; k0 < K; k0 += 16) {
        float4 av = *(const float4*)&A[(size_t)(m0 + am) * K + k0 + ak];
        As[ak + 0][am] = av.x; As[ak + 1][am] = av.y;
        As[ak + 2][am] = av.z; As[ak + 3][am] = av.w;
        *(float4*)&Bs[bk][bn] = *(const float4*)&Bm[(size_t)(k0 + bk) * N + n0 + bn];
        __syncthreads();
        #pragma unroll
        for (int k = 0; k < 16; ++k) {
            float4 a4 = *(float4*)&As[k][ty * 4];
            float4 b4 = *(float4*)&Bs[k][tx * 4];
            float a[4] = {a4.x, a4.y, a4.z, a4.w};
            float bb[4] = {b4.x, b4.y, b4.z, b4.w};
            #pragma unroll
            for (int r = 0; r < 4; ++r)
                #pragma unroll
                for (int cc = 0; cc < 4; ++cc)
                    acc[r][cc] = fmaf(a[r], bb[cc], acc[r][cc]);
        }
        __syncthreads();
    }
    #pragma unroll
    for (int r = 0; r < 4; ++r) {
        int row = m0 + ty * 4 + r;
        float4 o;
        float* po = &o.x;
        #pragma unroll
        for (int cc = 0; cc < 4; ++cc) {
            int col = n0 + tx * 4 + cc;
            float v = acc[r][cc] + bias[col];
            if (ACT == 1) v = fmaxf(v, 0.0f);
            po[cc] = v;
        }
        *(float4*)&C[(size_t)row * N + n0 + tx * 4] = o;
    }
}

// ---------------- LayerNorm ----------------
__global__ void ln_kernel(const float* __restrict__ X, const float* __restrict__ g,
                          const float* __restrict__ be, float* __restrict__ Y) {
    int b = blockIdx.x, t = threadIdx.x;
    __shared__ float r1[256], r2[256];
    float4 x = ((const float4*)(X + (size_t)b * HIDD))[t];
    r1[t] = x.x + x.y + x.z + x.w;
    r2[t] = x.x*x.x + x.y*x.y + x.z*x.z + x.w*x.w;
    __syncthreads();
    for (int s = 128; s > 0; s >>= 1) {
        if (t < s) { r1[t] += r1[t + s]; r2[t] += r2[t + s]; }
        __syncthreads();
    }
    float mu  = r1[0] * (1.0f / HIDD);
    float var = r2[0] * (1.0f / HIDD) - mu * mu;
    float rstd = rsqrtf(var + 1e-5f);
    float4 gg = ((const float4*)g)[t];
    float4 bb = ((const float4*)be)[t];
    float4 y;
    y.x = (x.x - mu) * rstd * gg.x + bb.x;
    y.y = (x.y - mu) * rstd * gg.y + bb.y;
    y.z = (x.z - mu) * rstd * gg.z + bb.z;
    y.w = (x.w - mu) * rstd * gg.w + bb.w;
    ((float4*)(Y + (size_t)b * HIDD))[t] = y;
}

// ---------------- propensity head ----------------
__global__ void prop_kernel(const float* __restrict__ Wt2, const float* __restrict__ bt2,
                            float* __restrict__ out) {
    int b = blockIdx.x, t = threadIdx.x;
    __shared__ float r0[256], r1[256];
    float v = g_tb[b * 256 + t];
    r0[t] = v * Wt2[t * 2 + 0];
    r1[t] = v * Wt2[t * 2 + 1];
    __syncthreads();
    for (int s = 128; s > 0; s >>= 1) {
        if (t < s) { r0[t] += r0[t + s]; r1[t] += r1[t + s]; }
        __syncthreads();
    }
    if (t == 0) {
        float l0 = r0[0] + bt2[0];
        float l1 = r1[0] + bt2[1];
        out[OFF_PL + b * 2 + 0] = l0;
        out[OFF_PL + b * 2 + 1] = l1;
        float m = fmaxf(l0, l1);
        float e0 = expf(l0 - m), e1 = expf(l1 - m);
        float d = 1.0f / (e0 + e1);
        out[OFF_PS + b * 2 + 0] = e0 * d;
        out[OFF_PS + b * 2 + 1] = e1 * d;
    }
}

// ---------------- outcome / targeted / counterfactual heads ----------------
__global__ void heads_kernel(const float* __restrict__ treat,
                             const float* __restrict__ Wo1, const float* __restrict__ Wo2,
                             const float* __restrict__ bo2,
                             const float* __restrict__ Wg1, const float* __restrict__ Wg2,
                             const float* __restrict__ bg2,
                             float* __restrict__ out) {
    int b = blockIdx.x, t = threadIdx.x;
    __shared__ float r[4][256];
    float obv = g_ob[b * 256 + t];
    float gbv = g_gb[b * 256 + t];
    float wo0 = Wo1[(size_t)512 * 256 + t];
    float wo1 = Wo1[(size_t)513 * 256 + t];
    float wg0 = Wg1[(size_t)512 * 256 + t];
    float wg1 = Wg1[(size_t)513 * 256 + t];
    float t0 = treat[b * 2 + 0], t1 = treat[b * 2 + 1];
    float wo2 = Wo2[t], wg2 = Wg2[t];
    r[0][t] = fmaxf(obv + t0 * wo0 + t1 * wo1, 0.0f) * wo2;
    r[1][t] = fmaxf(gbv + t0 * wg0 + t1 * wg1, 0.0f) * wg2;
    r[2][t] = fmaxf(obv + wo0, 0.0f) * wo2;
    r[3][t] = fmaxf(obv + wo1, 0.0f) * wo2;
    __syncthreads();
    for (int s = 128; s > 0; s >>= 1) {
        if (t < s) {
            r[0][t] += r[0][t + s]; r[1][t] += r[1][t + s];
            r[2][t] += r[2][t + s]; r[3][t] += r[3][t + s];
        }
        __syncthreads();
    }
    if (t == 0) {
        out[OFF_FACT + b]       = r[0][0] + bo2[0];
        out[OFF_TARG + b]       = r[1][0] + bg2[0];
        out[OFF_CF + b * 2 + 0] = r[2][0] + bo2[0];
        out[OFF_CF + b * 2 + 1] = r[3][0] + bo2[0];
    }
}

__global__ void copy_s_kernel(float* __restrict__ out) {
    int i = blockIdx.x * 256 + threadIdx.x;
    out[OFF_S + i] = g_s[i];
}

// ---------------- launch ----------------
extern "C" void kernel_launch(void* const* d_in, const int* in_sizes, int n_in,
                              void* d_out, int out_size) {
    const float* pf     = (const float*)d_in[0];
    const float* treat  = (const float*)d_in[1];
    const float* conf   = (const float*)d_in[2];
    const float* corpus = (const float*)d_in[3];
    const float* Wpe    = (const float*)d_in[4];
    const float* bpe    = (const float*)d_in[5];
    const float* W1     = (const float*)d_in[6];
    const float* b1     = (const float*)d_in[7];
    const float* g1     = (const float*)d_in[8];
    const float* be1    = (const float*)d_in[9];
    const float* W2     = (const float*)d_in[10];
    const float* b2     = (const float*)d_in[11];
    const float* g2     = (const float*)d_in[12];
    const float* be2    = (const float*)d_in[13];
    const float* W3     = (const float*)d_in[14];
    const float* b3     = (const float*)d_in[15];
    const float* Wo1    = (const float*)d_in[16];
    const float* bo1    = (const float*)d_in[17];
    const float* Wo2    = (const float*)d_in[18];
    const float* bo2    = (const float*)d_in[19];
    const float* Wt1    = (const float*)d_in[20];
    const float* bt1    = (const float*)d_in[21];
    const float* Wt2    = (const float*)d_in[22];
    const float* bt2    = (const float*)d_in[23];
    const float* Wg1    = (const float*)d_in[24];
    const float* bg1    = (const float*)d_in[25];
    const float* Wg2    = (const float*)d_in[26];
    const float* bg2    = (const float*)d_in[27];
    float* out = (float*)d_out;

    // resolve device-scratch addresses
    float *p_xin, *p_tmp, *p_h1, *p_h2, *p_s, *p_tb, *p_ob, *p_gb;
    cudaGetSymbolAddress((void**)&p_xin, g_xin);
    cudaGetSymbolAddress((void**)&p_tmp, g_tmp);
    cudaGetSymbolAddress((void**)&p_h1,  g_h1);
    cudaGetSymbolAddress((void**)&p_h2,  g_h2);
    cudaGetSymbolAddress((void**)&p_s,   g_s);
    cudaGetSymbolAddress((void**)&p_tb,  g_tb);
    cudaGetSymbolAddress((void**)&p_ob,  g_ob);
    cudaGetSymbolAddress((void**)&p_gb,  g_gb);

    cudaFuncSetAttribute(sim_kernel, cudaFuncAttributeMaxDynamicSharedMemorySize, SIM_SMEM);
    cudaFuncSetAttribute(merge_kernel, cudaFuncAttributeMaxDynamicSharedMemorySize, MERGE_SMEM);

    // retrieval
    pe_kernel<<<BATCH, 256>>>(pf, Wpe, bpe);
    convert_kernel<<<NPAD / 8, 256>>>(corpus);
    sim_kernel<<<NSPLIT, 512, SIM_SMEM>>>();
    merge_kernel<<<BATCH, 256, MERGE_SMEM>>>();
    rescore_kernel<<<BATCH, 512>>>(corpus, out);
    gather_kernel<<<BATCH, 256>>>(conf, corpus);

    // shared encoder
    gemm_kernel<1><<<dim3(HIDD / 64, BATCH / 64), 256>>>(p_xin, W1, b1, p_tmp,
                                                         BATCH, HIDD, SHIN);
    ln_kernel<<<BATCH, 256>>>(p_tmp, g1, be1, p_h1);
    gemm_kernel<1><<<dim3(HIDD / 64, BATCH / 64), 256>>>(p_h1, W2, b2, p_tmp,
                                                         BATCH, HIDD, HIDD);
    ln_kernel<<<BATCH, 256>>>(p_tmp, g2, be2, p_h2);
    gemm_kernel<0><<<dim3((HIDD / 2) / 64, BATCH / 64), 256>>>(p_h2, W3, b3, p_s,
                                                               BATCH, HIDD / 2, HIDD);

    // heads
    gemm_kernel<1><<<dim3(256 / 64, BATCH / 64), 256>>>(p_s, Wt1, bt1, p_tb,
                                                        BATCH, 256, HIDD / 2);
    gemm_kernel<0><<<dim3(256 / 64, BATCH / 64), 256>>>(p_s, Wo1, bo1, p_ob,
                                                        BATCH, 256, HIDD / 2);
    gemm_kernel<0><<<dim3(256 / 64, BATCH / 64), 256>>>(p_s, Wg1, bg1, p_gb,
                                                        BATCH, 256, HIDD / 2);
    prop_kernel<<<BATCH, 256>>>(Wt2, bt2, out);
    heads_kernel<<<BATCH, 256>>>(treat, Wo1, Wo2, bo2, Wg1, Wg2, bg2, out);
    copy_s_kernel<<<(BATCH * (HIDD / 2)) / 256, 256>>>(out);
}

// round 12
// speedup vs baseline: 2.9263x; 1.1389x over previous
#include <cuda_runtime.h>
#include <cuda_bf16.h>
#include <math.h>
#include <stdint.h>

// ---------------- problem constants ----------------
#define BATCH   512
#define CONFD   128
#define TREATD  2
#define EMBD    256
#define TOPKD   8
#define HIDD    1024
#define NCORP   500000
#define NSPLIT  152
#define NPAD    500096          // multiple of 128 (and 64)
#define NT64    (NPAD/64)       // 7814 corpus tiles of 64 rows
#define NL      NSPLIT          // 152 candidate lists per batch row (1 per CTA)
#define NCAND   16              // coarse candidates rescored exactly
#define SHIN    2176

// key for empty top-8 slot: encode(-inf) in high 32 bits -> decodes to -inf
#define KEY_EMPTY 0x007FFFFF00000000ULL

// output layout (float32)
#define OFF_FACT   0
#define OFF_TARG   512
#define OFF_CF     1024
#define OFF_PS     2048
#define OFF_PL     3072
#define OFF_SC     4096
#define OFF_IDX    8192
#define OFF_S      12288

// ---------------- static device scratch ----------------
__device__ __align__(16) __nv_bfloat16 g_corpusH[(size_t)NPAD * EMBD];  // row-major bf16
__device__ __align__(16) __nv_bfloat16 g_peH[BATCH * EMBD];             // row-major bf16
__device__ float g_peN[BATCH * EMBD];                // normalized pe fp32 row-major
__device__ __align__(16) float g_rnorm[NPAD];        // recip norms (0 for pad rows)
__device__ unsigned long long g_cand[(size_t)BATCH * NL * TOPKD];
__device__ int   g_coarse[BATCH * NCAND];
__device__ int   g_topidx[BATCH * TOPKD];
__device__ float g_xin[BATCH * SHIN];
__device__ float g_tmp[BATCH * HIDD];
__device__ float g_h1[BATCH * HIDD];
__device__ float g_h2[BATCH * HIDD];
__device__ float g_s[BATCH * (HIDD/2)];
__device__ float g_tb[BATCH * 256];
__device__ float g_ob[BATCH * 256];
__device__ float g_gb[BATCH * 256];

__device__ __forceinline__ uint32_t smem_u32(const void* p) {
    uint32_t a;
    asm("{ .reg .u64 t; cvta.to.shared.u64 t, %1; cvt.u32.u64 %0, t; }" : "=r"(a) : "l"(p));
    return a;
}

#define CP_ASYNC16(dst, src) \
    asm volatile("cp.async.cg.shared.global [%0], [%1], 16;" :: "r"(dst), "l"(src))
#define CP_COMMIT() asm volatile("cp.async.commit_group;" ::: "memory")
#define CP_WAIT1()  asm volatile("cp.async.wait_group 1;" ::: "memory")
#define CP_WAIT0()  asm volatile("cp.async.wait_group 0;" ::: "memory")

// ---------------- K1: pe = normalize(pf @ W_pe + b_pe) ----------------
__global__ void pe_kernel(const float* __restrict__ pf,
                          const float* __restrict__ Wpe,
                          const float* __restrict__ bpe) {
    int b = blockIdx.x;
    int e = threadIdx.x;          // 256
    __shared__ float x[CONFD + TREATD];
    __shared__ float red[256];
    if (e < CONFD + TREATD) x[e] = pf[b * (CONFD + TREATD) + e];
    __syncthreads();
    float acc = bpe[e];
    #pragma unroll 10
    for (int k = 0; k < CONFD + TREATD; ++k)
        acc = fmaf(x[k], Wpe[k * EMBD + e], acc);
    red[e] = acc * acc;
    __syncthreads();
    for (int s = 128; s > 0; s >>= 1) {
        if (e < s) red[e] += red[e + s];
        __syncthreads();
    }
    float v = acc / fmaxf(sqrtf(red[0]), 1e-12f);
    g_peN[b * EMBD + e] = v;
    g_peH[b * EMBD + e] = __float2bfloat16(v);
}

// ---------------- K2: corpus -> bf16 row-major + rnorm ----------------
__global__ void convert_kernel(const float* __restrict__ corpus) {
    int row  = blockIdx.x * 8 + (threadIdx.x >> 5);
    int lane = threadIdx.x & 31;
    if (row >= NPAD) return;
    float v[8];
    if (row < NCORP) {
        const float4* r4 = (const float4*)(corpus + (size_t)row * EMBD);
        float4 a = r4[lane * 2 + 0], b = r4[lane * 2 + 1];
        v[0]=a.x; v[1]=a.y; v[2]=a.z; v[3]=a.w; v[4]=b.x; v[5]=b.y; v[6]=b.z; v[7]=b.w;
    } else {
        #pragma unroll
        for (int i = 0; i < 8; ++i) v[i] = 0.0f;
    }
    float ss = 0.0f;
    #pragma unroll
    for (int i = 0; i < 8; ++i) ss = fmaf(v[i], v[i], ss);
    #pragma unroll
    for (int o = 16; o; o >>= 1) ss += __shfl_xor_sync(0xFFFFFFFFu, ss, o);
    if (lane == 0) g_rnorm[row] = (row < NCORP) ? (1.0f / fmaxf(sqrtf(ss), 1e-12f)) : 0.0f;
    union { __nv_bfloat16 h[8]; uint4 u; } pk;
    #pragma unroll
    for (int i = 0; i < 8; ++i) pk.h[i] = __float2bfloat16(v[i]);
    ((uint4*)g_corpusH)[(size_t)row * 32 + lane] = pk.u;
}

// ---------------- K3: mma.sync bf16 sim, cp.async double-buffered ----------------
// smem: pe [0,131072)  ct0 [131072,163840)  ct1 [163840,196608)  rns 2x256 [196608,197120)
#define SIM_SMEM 197120

#define PROC(karr, smin, simv, grow) do {                                             \
    if ((grow) < NCORP && (simv) >= (smin)) {                                         \
        uint32_t _u = __float_as_uint(simv);                                          \
        _u ^= (((int)_u) < 0) ? 0xFFFFFFFFu : 0x80000000u;                            \
        unsigned long long _k = ((unsigned long long)_u << 32)                        \
                              | (unsigned long long)(0xFFFFFFFFu - (uint32_t)(grow)); \
        if (_k > karr[7]) {                                                           \
            _Pragma("unroll")                                                         \
            for (int _q = 0; _q < 8; ++_q)                                            \
                if (_k > karr[_q]) {                                                  \
                    unsigned long long _t2 = karr[_q]; karr[_q] = _k; _k = _t2;       \
                }                                                                     \
            uint32_t _hi = (uint32_t)(karr[7] >> 32);                                 \
            _hi ^= (((int)_hi) < 0) ? 0x80000000u : 0xFFFFFFFFu;                      \
            smin = __uint_as_float(_hi);                                              \
        }                                                                             \
    }                                                                                 \
} while (0)

// merge my sorted-desc 8-list with partner lane's (xor mask) -> sorted-desc top-8
__device__ __forceinline__ void lane_merge8(unsigned long long k[8], int mask) {
    unsigned long long o[8], carr[8];
    #pragma unroll
    for (int j = 0; j < 8; ++j) o[j] = __shfl_xor_sync(0xFFFFFFFFu, k[j], mask);
    #pragma unroll
    for (int i = 0; i < 8; ++i) carr[i] = (k[i] > o[7 - i]) ? k[i] : o[7 - i];
#define CE(x, y) { unsigned long long _hi = carr[x] > carr[y] ? carr[x] : carr[y]; \
                   unsigned long long _lo = carr[x] > carr[y] ? carr[y] : carr[x]; \
                   carr[x] = _hi; carr[y] = _lo; }
    CE(0,4) CE(1,5) CE(2,6) CE(3,7)
    CE(0,2) CE(1,3) CE(4,6) CE(5,7)
    CE(0,1) CE(2,3) CE(4,5) CE(6,7)
#undef CE
    #pragma unroll
    for (int i = 0; i < 8; ++i) k[i] = carr[i];
}

__device__ __forceinline__ void stage_tile(uint32_t smb, int tile, int buf, int t) {
    const char* src = (const char*)g_corpusH + (size_t)tile * 32768;
    #pragma unroll
    for (int i = 0; i < 4; ++i) {
        int u = t + i * 512;                   // 2048 uint4 total
        int r = u >> 5, un = u & 31;
        uint32_t dst = smb + 131072 + (uint32_t)buf * 32768 + r * 512
                     + (((un * 16) ^ ((r & 7) << 4)));
        CP_ASYNC16(dst, src + (size_t)u * 16);
    }
    if (t < 16)
        CP_ASYNC16(smb + 196608 + (uint32_t)buf * 256 + t * 16,
                   (const char*)(g_rnorm + (size_t)tile * 64) + t * 16);
    CP_COMMIT();
}

__global__ void __launch_bounds__(512, 1) sim_kernel() {
    extern __shared__ __align__(16) unsigned char sm[];
    const uint32_t smb = smem_u32(sm);
    const int t = threadIdx.x, lane = t & 31, w = t >> 5;   // w = mblk (16 warps)
    const int c = blockIdx.x;
    const int gid = lane >> 2, tid4 = lane & 3;
    const int T0 = (c * NT64) / NSPLIT, T1 = ((c + 1) * NT64) / NSPLIT;

    const uint32_t swz   = (uint32_t)(lane & 7) << 4;
    const uint32_t offA0 = (uint32_t)((lane >> 4) * 16);
    const uint32_t Abase = smb + (uint32_t)(w * 16 + (lane & 15)) * 512;
    const int      nb    = (lane & 7) | (((lane >> 4) & 1) << 3);
    const uint32_t koffB = (uint32_t)(((lane >> 3) & 1) * 16);

    for (int h = 0; h < 2; ++h) {
        // stage pe half (256 rows x 512B), swizzled
        {
            const uint4* src = (const uint4*)g_peH + (size_t)(h * 256) * 32;
            #pragma unroll
            for (int i = 0; i < 16; ++i) {
                int u = t + i * 512;            // 8192 uint4
                int r = u >> 5, un = u & 31;
                *(uint4*)(sm + r * 512 + ((un * 16) ^ ((r & 7) << 4))) = src[u];
            }
        }
        unsigned long long k8a[8], k8b[8];
        #pragma unroll
        for (int q = 0; q < 8; ++q) { k8a[q] = KEY_EMPTY; k8b[q] = KEY_EMPTY; }
        float smin0 = -INFINITY, smin1 = -INFINITY;

        stage_tile(smb, T0, 0, t);
        __syncthreads();   // pe visible

        int buf = 0;
        for (int tile = T0; tile < T1; ++tile) {
            if (tile + 1 < T1) { stage_tile(smb, tile + 1, buf ^ 1, t); CP_WAIT1(); }
            else               { CP_WAIT0(); }
            __syncthreads();   // current buf complete for all threads

            const uint32_t Bct = smb + 131072 + (uint32_t)buf * 32768 + (uint32_t)nb * 512;
            const float* rns_s = (const float*)(sm + 196608 + buf * 256);

            float acc[8][4];
            #pragma unroll
            for (int nf = 0; nf < 8; ++nf)
                #pragma unroll
                for (int i = 0; i < 4; ++i) acc[nf][i] = 0.0f;

            #pragma unroll
            for (int ks = 0; ks < 16; ++ks) {
                uint32_t a0, a1, a2, a3;
                uint32_t aaddr = Abase + (((uint32_t)(ks * 32) + offA0) ^ swz);
                asm volatile("ldmatrix.sync.aligned.m8n8.x4.shared.b16 {%0,%1,%2,%3}, [%4];"
                             : "=r"(a0), "=r"(a1), "=r"(a2), "=r"(a3) : "r"(aaddr));
                uint32_t koff = ((uint32_t)(ks * 32) + koffB) ^ swz;
                #pragma unroll
                for (int np = 0; np < 4; ++np) {
                    uint32_t b0, b1, b2, b3;
                    uint32_t baddr = Bct + (uint32_t)(np * 8192) + koff;
                    asm volatile("ldmatrix.sync.aligned.m8n8.x4.shared.b16 {%0,%1,%2,%3}, [%4];"
                                 : "=r"(b0), "=r"(b1), "=r"(b2), "=r"(b3) : "r"(baddr));
                    asm volatile("mma.sync.aligned.m16n8k16.row.col.f32.bf16.bf16.f32 "
                                 "{%0,%1,%2,%3}, {%4,%5,%6,%7}, {%8,%9}, {%0,%1,%2,%3};"
                                 : "+f"(acc[2*np][0]), "+f"(acc[2*np][1]),
                                   "+f"(acc[2*np][2]), "+f"(acc[2*np][3])
                                 : "r"(a0), "r"(a1), "r"(a2), "r"(a3), "r"(b0), "r"(b1));
                    asm volatile("mma.sync.aligned.m16n8k16.row.col.f32.bf16.bf16.f32 "
                                 "{%0,%1,%2,%3}, {%4,%5,%6,%7}, {%8,%9}, {%0,%1,%2,%3};"
                                 : "+f"(acc[2*np+1][0]), "+f"(acc[2*np+1][1]),
                                   "+f"(acc[2*np+1][2]), "+f"(acc[2*np+1][3])
                                 : "r"(a0), "r"(a1), "r"(a2), "r"(a3), "r"(b2), "r"(b3));
                }
            }

            // epilogue: rows gid / gid+8; cols nf*8 + tid4*2 + {0,1}
            #pragma unroll
            for (int nf = 0; nf < 8; ++nf) {
                int col0 = nf * 8 + tid4 * 2;
                float rn0 = rns_s[col0], rn1 = rns_s[col0 + 1];
                int grow0 = tile * 64 + col0;
                float s00 = acc[nf][0] * rn0;
                float s01 = acc[nf][1] * rn1;
                float s10 = acc[nf][2] * rn0;
                float s11 = acc[nf][3] * rn1;
                PROC(k8a, smin0, s00, grow0);
                PROC(k8a, smin0, s01, grow0 + 1);
                PROC(k8b, smin1, s10, grow0);
                PROC(k8b, smin1, s11, grow0 + 1);
            }
            __syncthreads();   // done reading buf before it is re-staged
            buf ^= 1;
        }

        // merge the 4 lanes of each quad -> one list per row, flush
        lane_merge8(k8a, 1); lane_merge8(k8a, 2);
        lane_merge8(k8b, 1); lane_merge8(k8b, 2);
        if (tid4 == 0) {
            int row0 = h * 256 + w * 16 + gid;
            unsigned long long* d0 = g_cand + ((size_t)row0 * NL + c) * TOPKD;
            unsigned long long* d1 = g_cand + ((size_t)(row0 + 8) * NL + c) * TOPKD;
            #pragma unroll
            for (int q = 0; q < 8; ++q) { d0[q] = k8a[q]; d1[q] = k8b[q]; }
        }
        __syncthreads();       // before pe restage next half
    }
}

// ---------------- K4: merge coarse candidates -> top-16 per row ----------------
__global__ void merge_kernel() {
    __shared__ unsigned long long cs[NL * TOPKD];   // 1216
    __shared__ unsigned long long rk[256];
    __shared__ int rp[256];
    const int b = blockIdx.x;
    const int t = threadIdx.x;     // 256
    const int NC = NL * TOPKD;     // 1216
    for (int p = t; p < NC; p += 256) cs[p] = g_cand[(size_t)b * NC + p];
    __syncthreads();
    for (int r = 0; r < NCAND; ++r) {
        unsigned long long bk = 0ULL; int bp = 0;
        for (int p = t; p < NC; p += 256)
            if (cs[p] > bk) { bk = cs[p]; bp = p; }
        rk[t] = bk; rp[t] = bp;
        __syncthreads();
        for (int s = 128; s > 0; s >>= 1) {
            if (t < s && rk[t + s] > rk[t]) { rk[t] = rk[t + s]; rp[t] = rp[t + s]; }
            __syncthreads();
        }
        if (t == 0) {
            g_coarse[b * NCAND + r] = (int)(0xFFFFFFFFu - (uint32_t)rk[0]);
            cs[rp[0]] = 0ULL;
        }
        __syncthreads();
    }
}

// ---------------- K5: exact fp32 rescore of 16 candidates -> top-8 ----------------
__global__ void rescore_kernel(const float* __restrict__ corpus, float* __restrict__ out) {
    const int b = blockIdx.x;
    const int w = threadIdx.x >> 5;      // 16 warps = 16 candidates
    const int lane = threadIdx.x & 31;
    __shared__ float sc[NCAND];
    __shared__ int   si[NCAND];
    int idx = g_coarse[b * NCAND + w];
    const float4* cr = (const float4*)(corpus + (size_t)idx * EMBD);
    const float4* pr = (const float4*)(g_peN + (size_t)b * EMBD);
    float dot = 0.0f, ss = 0.0f;
    #pragma unroll
    for (int i = 0; i < 2; ++i) {
        float4 cv = cr[lane * 2 + i];
        float4 pv = pr[lane * 2 + i];
        dot = fmaf(pv.x, cv.x, fmaf(pv.y, cv.y, fmaf(pv.z, cv.z, fmaf(pv.w, cv.w, dot))));
        ss  = fmaf(cv.x, cv.x, fmaf(cv.y, cv.y, fmaf(cv.z, cv.z, fmaf(cv.w, cv.w, ss))));
    }
    #pragma unroll
    for (int o = 16; o; o >>= 1) {
        dot += __shfl_xor_sync(0xFFFFFFFFu, dot, o);
        ss  += __shfl_xor_sync(0xFFFFFFFFu, ss,  o);
    }
    if (lane == 0) { sc[w] = dot / fmaxf(sqrtf(ss), 1e-12f); si[w] = idx; }
    __syncthreads();
    if (threadIdx.x == 0) {
        #pragma unroll
        for (int r = 0; r < TOPKD; ++r) {
            int best = r;
            for (int q = r + 1; q < NCAND; ++q)
                if (sc[q] > sc[best] || (sc[q] == sc[best] && si[q] < si[best])) best = q;
            float tv = sc[r]; sc[r] = sc[best]; sc[best] = tv;
            int   ti = si[r]; si[r] = si[best]; si[best] = ti;
            out[OFF_SC  + b * TOPKD + r] = sc[r];
            out[OFF_IDX + b * TOPKD + r] = (float)si[r];
            g_topidx[b * TOPKD + r] = si[r];
        }
    }
}

// ---------------- K6: build shared_in = [conf | retrieved(raw)] ----------------
__global__ void gather_kernel(const float* __restrict__ conf,
                              const float* __restrict__ corpus) {
    int b = blockIdx.x, t = threadIdx.x;   // 256
    if (t < CONFD) g_xin[b * SHIN + t] = conf[b * CONFD + t];
    #pragma unroll
    for (int ki = 0; ki < TOPKD; ++ki) {
        int j = g_topidx[b * TOPKD + ki];
        g_xin[b * SHIN + CONFD + ki * EMBD + t] = corpus[(size_t)j * EMBD + t];
    }
}

// ---------------- generic fp32 GEMM (f32x2 inner): C = act(A@B + bias) ----------------
#define FMA2(accv, av, bv) \
    asm("fma.rn.f32x2 %0, %1, %2, %0;" : "+l"(accv) : "l"(av), "l"(bv))
#define PACK2(dv, lo, hi) \
    asm("mov.b64 %0, {%1, %2};" : "=l"(dv) : "f"(lo), "f"(hi))

template <int ACT>
__global__ void __launch_bounds__(256)
gemm_kernel(const float* __restrict__ A, const float* __restrict__ Bm,
            const float* __restrict__ bias, float* __restrict__ C,
            int M, int N, int K) {
    __shared__ float As[16][68];
    __shared__ float Bs[16][64];
    const int tx = threadIdx.x & 15;
    const int ty = threadIdx.x >> 4;
    const int m0 = blockIdx.y * 64;
    const int n0 = blockIdx.x * 64;
    unsigned long long acc2[4][4];
    #pragma unroll
    for (int r = 0; r < 4; ++r)
        #pragma unroll
        for (int cc = 0; cc < 4; ++cc) acc2[r][cc] = 0ULL;

    const int p = threadIdx.x * 4;
    const int am = p >> 4, ak = p & 15;
    const int bk = p >> 6, bn = p & 63;
    for (int k0 = 0; k0 < K; k0 += 16) {
        float4 av = *(const float4*)&A[(size_t)(m0 + am) * K + k0 + ak];
        As[ak + 0][am] = av.x; As[ak + 1][am] = av.y;
        As[ak + 2][am] = av.z; As[ak + 3][am] = av.w;
        *(float4*)&Bs[bk][bn] = *(const float4*)&Bm[(size_t)(k0 + bk) * N + n0 + bn];
        __syncthreads();
        #pragma unroll
        for (int k = 0; k < 16; k += 2) {
            float4 a0 = *(float4*)&As[k][ty * 4];
            float4 a1 = *(float4*)&As[k + 1][ty * 4];
            float4 b0 = *(float4*)&Bs[k][tx * 4];
            float4 b1 = *(float4*)&Bs[k + 1][tx * 4];
            unsigned long long A2[4], B2[4];
            PACK2(A2[0], a0.x, a1.x); PACK2(A2[1], a0.y, a1.y);
            PACK2(A2[2], a0.z, a1.z); PACK2(A2[3], a0.w, a1.w);
            PACK2(B2[0], b0.x, b1.x); PACK2(B2[1], b0.y, b1.y);
            PACK2(B2[2], b0.z, b1.z); PACK2(B2[3], b0.w, b1.w);
            #pragma unroll
            for (int r = 0; r < 4; ++r)
                #pragma unroll
                for (int cc = 0; cc < 4; ++cc)
                    FMA2(acc2[r][cc], A2[r], B2[cc]);
        }
        __syncthreads();
    }
    #pragma unroll
    for (int r = 0; r < 4; ++r) {
        int row = m0 + ty * 4 + r;
        float4 o;
        float* po = &o.x;
        #pragma unroll
        for (int cc = 0; cc < 4; ++cc) {
            int col = n0 + tx * 4 + cc;
            float lo, hi;
            asm("mov.b64 {%0, %1}, %2;" : "=f"(lo), "=f"(hi) : "l"(acc2[r][cc]));
            float v = lo + hi + bias[col];
            if (ACT == 1) v = fmaxf(v, 0.0f);
            po[cc] = v;
        }
        *(float4*)&C[(size_t)row * N + n0 + tx * 4] = o;
    }
}

// ---------------- LayerNorm ----------------
__global__ void ln_kernel(const float* __restrict__ X, const float* __restrict__ g,
                          const float* __restrict__ be, float* __restrict__ Y) {
    int b = blockIdx.x, t = threadIdx.x;
    __shared__ float r1[256], r2[256];
    float4 x = ((const float4*)(X + (size_t)b * HIDD))[t];
    r1[t] = x.x + x.y + x.z + x.w;
    r2[t] = x.x*x.x + x.y*x.y + x.z*x.z + x.w*x.w;
    __syncthreads();
    for (int s = 128; s > 0; s >>= 1) {
        if (t < s) { r1[t] += r1[t + s]; r2[t] += r2[t + s]; }
        __syncthreads();
    }
    float mu  = r1[0] * (1.0f / HIDD);
    float var = r2[0] * (1.0f / HIDD) - mu * mu;
    float rstd = rsqrtf(var + 1e-5f);
    float4 gg = ((const float4*)g)[t];
    float4 bb = ((const float4*)be)[t];
    float4 y;
    y.x = (x.x - mu) * rstd * gg.x + bb.x;
    y.y = (x.y - mu) * rstd * gg.y + bb.y;
    y.z = (x.z - mu) * rstd * gg.z + bb.z;
    y.w = (x.w - mu) * rstd * gg.w + bb.w;
    ((float4*)(Y + (size_t)b * HIDD))[t] = y;
}

// ---------------- propensity head ----------------
__global__ void prop_kernel(const float* __restrict__ Wt2, const float* __restrict__ bt2,
                            float* __restrict__ out) {
    int b = blockIdx.x, t = threadIdx.x;
    __shared__ float r0[256], r1[256];
    float v = g_tb[b * 256 + t];
    r0[t] = v * Wt2[t * 2 + 0];
    r1[t] = v * Wt2[t * 2 + 1];
    __syncthreads();
    for (int s = 128; s > 0; s >>= 1) {
        if (t < s) { r0[t] += r0[t + s]; r1[t] += r1[t + s]; }
        __syncthreads();
    }
    if (t == 0) {
        float l0 = r0[0] + bt2[0];
        float l1 = r1[0] + bt2[1];
        out[OFF_PL + b * 2 + 0] = l0;
        out[OFF_PL + b * 2 + 1] = l1;
        float m = fmaxf(l0, l1);
        float e0 = expf(l0 - m), e1 = expf(l1 - m);
        float d = 1.0f / (e0 + e1);
        out[OFF_PS + b * 2 + 0] = e0 * d;
        out[OFF_PS + b * 2 + 1] = e1 * d;
    }
}

// ---------------- outcome / targeted / counterfactual heads ----------------
__global__ void heads_kernel(const float* __restrict__ treat,
                             const float* __restrict__ Wo1, const float* __restrict__ Wo2,
                             const float* __restrict__ bo2,
                             const float* __restrict__ Wg1, const float* __restrict__ Wg2,
                             const float* __restrict__ bg2,
                             float* __restrict__ out) {
    int b = blockIdx.x, t = threadIdx.x;
    __shared__ float r[4][256];
    float obv = g_ob[b * 256 + t];
    float gbv = g_gb[b * 256 + t];
    float wo0 = Wo1[(size_t)512 * 256 + t];
    float wo1 = Wo1[(size_t)513 * 256 + t];
    float wg0 = Wg1[(size_t)512 * 256 + t];
    float wg1 = Wg1[(size_t)513 * 256 + t];
    float t0 = treat[b * 2 + 0], t1 = treat[b * 2 + 1];
    float wo2 = Wo2[t], wg2 = Wg2[t];
    r[0][t] = fmaxf(obv + t0 * wo0 + t1 * wo1, 0.0f) * wo2;
    r[1][t] = fmaxf(gbv + t0 * wg0 + t1 * wg1, 0.0f) * wg2;
    r[2][t] = fmaxf(obv + wo0, 0.0f) * wo2;
    r[3][t] = fmaxf(obv + wo1, 0.0f) * wo2;
    __syncthreads();
    for (int s = 128; s > 0; s >>= 1) {
        if (t < s) {
            r[0][t] += r[0][t + s]; r[1][t] += r[1][t + s];
            r[2][t] += r[2][t + s]; r[3][t] += r[3][t + s];
        }
        __syncthreads();
    }
    if (t == 0) {
        out[OFF_FACT + b]       = r[0][0] + bo2[0];
        out[OFF_TARG + b]       = r[1][0] + bg2[0];
        out[OFF_CF + b * 2 + 0] = r[2][0] + bo2[0];
        out[OFF_CF + b * 2 + 1] = r[3][0] + bo2[0];
    }
}

__global__ void copy_s_kernel(float* __restrict__ out) {
    int i = blockIdx.x * 256 + threadIdx.x;
    out[OFF_S + i] = g_s[i];
}

// ---------------- launch ----------------
extern "C" void kernel_launch(void* const* d_in, const int* in_sizes, int n_in,
                              void* d_out, int out_size) {
    const float* pf     = (const float*)d_in[0];
    const float* treat  = (const float*)d_in[1];
    const float* conf   = (const float*)d_in[2];
    const float* corpus = (const float*)d_in[3];
    const float* Wpe    = (const float*)d_in[4];
    const float* bpe    = (const float*)d_in[5];
    const float* W1     = (const float*)d_in[6];
    const float* b1     = (const float*)d_in[7];
    const float* g1     = (const float*)d_in[8];
    const float* be1    = (const float*)d_in[9];
    const float* W2     = (const float*)d_in[10];
    const float* b2     = (const float*)d_in[11];
    const float* g2     = (const float*)d_in[12];
    const float* be2    = (const float*)d_in[13];
    const float* W3     = (const float*)d_in[14];
    const float* b3     = (const float*)d_in[15];
    const float* Wo1    = (const float*)d_in[16];
    const float* bo1    = (const float*)d_in[17];
    const float* Wo2    = (const float*)d_in[18];
    const float* bo2    = (const float*)d_in[19];
    const float* Wt1    = (const float*)d_in[20];
    const float* bt1    = (const float*)d_in[21];
    const float* Wt2    = (const float*)d_in[22];
    const float* bt2    = (const float*)d_in[23];
    const float* Wg1    = (const float*)d_in[24];
    const float* bg1    = (const float*)d_in[25];
    const float* Wg2    = (const float*)d_in[26];
    const float* bg2    = (const float*)d_in[27];
    float* out = (float*)d_out;

    // resolve device-scratch addresses
    float *p_xin, *p_tmp, *p_h1, *p_h2, *p_s, *p_tb, *p_ob, *p_gb;
    cudaGetSymbolAddress((void**)&p_xin, g_xin);
    cudaGetSymbolAddress((void**)&p_tmp, g_tmp);
    cudaGetSymbolAddress((void**)&p_h1,  g_h1);
    cudaGetSymbolAddress((void**)&p_h2,  g_h2);
    cudaGetSymbolAddress((void**)&p_s,   g_s);
    cudaGetSymbolAddress((void**)&p_tb,  g_tb);
    cudaGetSymbolAddress((void**)&p_ob,  g_ob);
    cudaGetSymbolAddress((void**)&p_gb,  g_gb);

    cudaFuncSetAttribute(sim_kernel, cudaFuncAttributeMaxDynamicSharedMemorySize, SIM_SMEM);

    // retrieval
    pe_kernel<<<BATCH, 256>>>(pf, Wpe, bpe);
    convert_kernel<<<NPAD / 8, 256>>>(corpus);
    sim_kernel<<<NSPLIT, 512, SIM_SMEM>>>();
    merge_kernel<<<BATCH, 256>>>();
    rescore_kernel<<<BATCH, 512>>>(corpus, out);
    gather_kernel<<<BATCH, 256>>>(conf, corpus);

    // shared encoder
    gemm_kernel<1><<<dim3(HIDD / 64, BATCH / 64), 256>>>(p_xin, W1, b1, p_tmp,
                                                         BATCH, HIDD, SHIN);
    ln_kernel<<<BATCH, 256>>>(p_tmp, g1, be1, p_h1);
    gemm_kernel<1><<<dim3(HIDD / 64, BATCH / 64), 256>>>(p_h1, W2, b2, p_tmp,
                                                         BATCH, HIDD, HIDD);
    ln_kernel<<<BATCH, 256>>>(p_tmp, g2, be2, p_h2);
    gemm_kernel<0><<<dim3((HIDD / 2) / 64, BATCH / 64), 256>>>(p_h2, W3, b3, p_s,
                                                               BATCH, HIDD / 2, HIDD);

    // heads
    gemm_kernel<1><<<dim3(256 / 64, BATCH / 64), 256>>>(p_s, Wt1, bt1, p_tb,
                                                        BATCH, 256, HIDD / 2);
    gemm_kernel<0><<<dim3(256 / 64, BATCH / 64), 256>>>(p_s, Wo1, bo1, p_ob,
                                                        BATCH, 256, HIDD / 2);
    gemm_kernel<0><<<dim3(256 / 64, BATCH / 64), 256>>>(p_s, Wg1, bg1, p_gb,
                                                        BATCH, 256, HIDD / 2);
    prop_kernel<<<BATCH, 256>>>(Wt2, bt2, out);
    heads_kernel<<<BATCH, 256>>>(treat, Wo1, Wo2, bo2, Wg1, Wg2, bg2, out);
    copy_s_kernel<<<(BATCH * (HIDD / 2)) / 256, 256>>>(out);
}